// round 11
// baseline (speedup 1.0000x reference)
#include <cuda_runtime.h>
#include <cuda_bf16.h>
#include <cuda_fp16.h>
#include <stdint.h>
#include <math.h>

#define B_ 64
#define T_ 512
#define I_ 256
#define H_ 1024
#define G_ 4096
#define O_ 256

// ---------------- device scratch ----------------
__device__ float g_xproj0[(size_t)T_ * B_ * G_];   // [t][b][4H] fp32
__device__ float g_xproj1[(size_t)T_ * B_ * G_];
__device__ __nv_bfloat16 g_xhi[(size_t)B_ * T_ * I_];
__device__ __nv_bfloat16 g_xlo[(size_t)B_ * T_ * I_];
__device__ __nv_bfloat16 g_wih0hi[(size_t)G_ * I_];
__device__ __nv_bfloat16 g_wih0lo[(size_t)G_ * I_];
__device__ __nv_bfloat16 g_wih1hi[(size_t)G_ * H_];
__device__ __nv_bfloat16 g_wih1lo[(size_t)G_ * H_];
__device__ __nv_bfloat16 g_hs0hi[(size_t)T_ * B_ * H_];  // layer-0 outputs hi/lo (for proj)
__device__ __nv_bfloat16 g_hs0lo[(size_t)T_ * B_ * H_];
__device__ __half g_hf[2][B_ * H_];                // recurrent h, single fp16
__device__ float g_hlast[B_ * H_];                 // fp32 final h for FC
__device__ unsigned int g_cnt[8 * 32];             // 8 group counters, 128B padded
                                                   // group g = blocks 16g..16g+15 = h-chunk g

// ---------------- helpers ----------------
__device__ __forceinline__ void ldsm4(uint32_t* r, uint32_t addr) {
    asm volatile("ldmatrix.sync.aligned.m8n8.x4.shared.b16 {%0,%1,%2,%3}, [%4];"
        : "=r"(r[0]), "=r"(r[1]), "=r"(r[2]), "=r"(r[3]) : "r"(addr));
}
__device__ __forceinline__ void ldsm2(uint32_t* r, uint32_t addr) {
    asm volatile("ldmatrix.sync.aligned.m8n8.x2.shared.b16 {%0,%1}, [%2];"
        : "=r"(r[0]), "=r"(r[1]) : "r"(addr));
}
// bf16 mma (projections)
__device__ __forceinline__ void mma16816(float* c, const uint32_t* a, const uint32_t* b) {
    asm volatile("mma.sync.aligned.m16n8k16.row.col.f32.bf16.bf16.f32 "
        "{%0,%1,%2,%3}, {%4,%5,%6,%7}, {%8,%9}, {%0,%1,%2,%3};"
        : "+f"(c[0]), "+f"(c[1]), "+f"(c[2]), "+f"(c[3])
        : "r"(a[0]), "r"(a[1]), "r"(a[2]), "r"(a[3]), "r"(b[0]), "r"(b[1]));
}
// fp16 mma (recurrence)
__device__ __forceinline__ void mma16816h(float* c, const uint32_t* a, const uint32_t* b) {
    asm volatile("mma.sync.aligned.m16n8k16.row.col.f32.f16.f16.f32 "
        "{%0,%1,%2,%3}, {%4,%5,%6,%7}, {%8,%9}, {%0,%1,%2,%3};"
        : "+f"(c[0]), "+f"(c[1]), "+f"(c[2]), "+f"(c[3])
        : "r"(a[0]), "r"(a[1]), "r"(a[2]), "r"(a[3]), "r"(b[0]), "r"(b[1]));
}
__device__ __forceinline__ uint32_t cvta_s(const void* p) {
    return (uint32_t)__cvta_generic_to_shared(p);
}
__device__ __forceinline__ unsigned int ld_acq(const unsigned int* p) {
    unsigned int v;
    asm volatile("ld.acquire.gpu.u32 %0, [%1];" : "=r"(v) : "l"(p) : "memory");
    return v;
}
#define CP_ASYNC16(d, s) asm volatile("cp.async.cg.shared.global [%0], [%1], 16;" :: "r"(d), "l"(s))
#define CP_COMMIT()      asm volatile("cp.async.commit_group;" ::: "memory")
#define CP_WAIT1()       asm volatile("cp.async.wait_group 1;" ::: "memory")
#define CP_WAIT0()       asm volatile("cp.async.wait_group 0;" ::: "memory")

// ---------------- init ----------------
__global__ void init_kernel() {
    int idx = blockIdx.x * blockDim.x + threadIdx.x;
    if (idx < 8 * 32) g_cnt[idx] = 0u;
    __half z = __float2half(0.f);
    int n = 2 * B_ * H_;
    __half* ph = (__half*)g_hf;
    for (int i = idx; i < n; i += gridDim.x * blockDim.x) ph[i] = z;
}

// ---------------- fp32 -> bf16 hi/lo split (projection operands) ------------
__global__ void split_kernel(const float* __restrict__ src,
                             __nv_bfloat16* __restrict__ hi,
                             __nv_bfloat16* __restrict__ lo, int n4) {
    int i = blockIdx.x * blockDim.x + threadIdx.x;
    if (i >= n4) return;
    float4 v = ((const float4*)src)[i];
    __nv_bfloat16 h0 = __float2bfloat16(v.x);
    __nv_bfloat16 h1 = __float2bfloat16(v.y);
    __nv_bfloat16 h2 = __float2bfloat16(v.z);
    __nv_bfloat16 h3 = __float2bfloat16(v.w);
    __nv_bfloat162 a, b;
    a.x = h0; a.y = h1; b.x = h2; b.y = h3;
    ((__nv_bfloat162*)hi)[2 * i] = a;
    ((__nv_bfloat162*)hi)[2 * i + 1] = b;
    a.x = __float2bfloat16(v.x - __bfloat162float(h0));
    a.y = __float2bfloat16(v.y - __bfloat162float(h1));
    b.x = __float2bfloat16(v.z - __bfloat162float(h2));
    b.y = __float2bfloat16(v.w - __bfloat162float(h3));
    ((__nv_bfloat162*)lo)[2 * i] = a;
    ((__nv_bfloat162*)lo)[2 * i + 1] = b;
}

// ---------------- split-bf16 MMA projection GEMM (unchanged) ----------------
__global__ __launch_bounds__(256) void mma_xproj(
    const __nv_bfloat16* __restrict__ Ahi, const __nv_bfloat16* __restrict__ Alo,
    const __nv_bfloat16* __restrict__ Whi, const __nv_bfloat16* __restrict__ Wlo,
    const float* __restrict__ b1, const float* __restrict__ b2,
    float* __restrict__ Cout, int K, int mode)
{
    __shared__ __nv_bfloat16 sAhi[128 * 40], sAlo[128 * 40];
    __shared__ __nv_bfloat16 sBhi[64 * 40],  sBlo[64 * 40];
    __shared__ float sBias[64];

    int tid = threadIdx.x;
    int n0 = blockIdx.x * 64;
    int m0 = blockIdx.y * 128;
    int w = tid >> 5, lane = tid & 31;
    int r0 = w * 16;

    if (tid < 64) sBias[tid] = b1[n0 + tid] + b2[n0 + tid];

    float acc[8][4];
#pragma unroll
    for (int i = 0; i < 8; i++)
#pragma unroll
        for (int j = 0; j < 4; j++) acc[i][j] = 0.f;

    size_t arow[2]; int aoff[2];
#pragma unroll
    for (int it = 0; it < 2; it++) {
        int idx = tid + it * 256;
        int r = idx >> 2, seg = idx & 3;
        int m = m0 + r;
        arow[it] = (mode == 0) ? ((size_t)(m & 63) * T_ + (size_t)(m >> 6)) * (size_t)K + (size_t)(seg * 8)
                               : (size_t)m * (size_t)K + (size_t)(seg * 8);
        aoff[it] = r * 40 + seg * 8;
    }
    int br = tid >> 2, bseg = tid & 3;
    size_t brow = (size_t)(n0 + br) * (size_t)K + (size_t)(bseg * 8);
    int boff = br * 40 + bseg * 8;

    int lrA = (lane & 7) + (lane & 8);
    int lcA = (lane & 16) ? 8 : 0;
    uint32_t aHiB = cvta_s(&sAhi[(r0 + lrA) * 40 + lcA]);
    uint32_t aLoB = cvta_s(&sAlo[(r0 + lrA) * 40 + lcA]);
    int lrB = lane & 7;
    int lcB = (lane & 8) ? 8 : 0;
    uint32_t bHiB = cvta_s(&sBhi[lrB * 40 + lcB]);
    uint32_t bLoB = cvta_s(&sBlo[lrB * 40 + lcB]);

    for (int kc = 0; kc < K; kc += 32) {
        __syncthreads();
#pragma unroll
        for (int it = 0; it < 2; it++) {
            *(uint4*)&sAhi[aoff[it]] = *(const uint4*)(Ahi + arow[it] + kc);
            *(uint4*)&sAlo[aoff[it]] = *(const uint4*)(Alo + arow[it] + kc);
        }
        *(uint4*)&sBhi[boff] = *(const uint4*)(Whi + brow + kc);
        *(uint4*)&sBlo[boff] = *(const uint4*)(Wlo + brow + kc);
        __syncthreads();
#pragma unroll
        for (int ks = 0; ks < 2; ks++) {
            int k0 = ks * 16;
            uint32_t ah[4], al[4];
            ldsm4(ah, aHiB + (uint32_t)(k0 * 2));
            ldsm4(al, aLoB + (uint32_t)(k0 * 2));
#pragma unroll
            for (int nt = 0; nt < 8; nt++) {
                uint32_t bh[2], bl[2];
                uint32_t off = (uint32_t)(nt * 8 * 40 + k0) * 2u;
                ldsm2(bh, bHiB + off);
                ldsm2(bl, bLoB + off);
                mma16816(acc[nt], ah, bh);
                mma16816(acc[nt], ah, bl);
                mma16816(acc[nt], al, bh);
            }
        }
    }

    int g = lane >> 2, tq = lane & 3;
#pragma unroll
    for (int nt = 0; nt < 8; nt++) {
        int col = nt * 8 + tq * 2;
        float bb0 = sBias[col], bb1 = sBias[col + 1];
        size_t mA = (size_t)(m0 + r0 + g) * G_ + n0 + col;
        size_t mB = (size_t)(m0 + r0 + g + 8) * G_ + n0 + col;
        float2 v0 = make_float2(acc[nt][0] + bb0, acc[nt][1] + bb1);
        float2 v1 = make_float2(acc[nt][2] + bb0, acc[nt][3] + bb1);
        *(float2*)&Cout[mA] = v0;
        *(float2*)&Cout[mB] = v1;
    }
}

// ---------------- persistent LSTM recurrence: fp16, chunk-dataflow ----------
// 128 blocks x 512 threads. Warp w: rowg=w&3, colg=(w>>2)&1, ks=w>>3.
// Block bid owns h-cols [8bid, 8bid+8). Group g = blocks [16g,16g+16) produce
// h-chunk g (cols [128g,128g+128)). Each block posts ONE atomic per step to
// its group counter; thread 0 acquire-polls the producer group of each chunk
// before its cp.async prefetch (look-ahead register scheme hides L2 latency).
extern __shared__ char smem_dyn[];
__global__ __launch_bounds__(512) void lstm_recur_mma(
    const float* __restrict__ xproj,   // [T][B][4H] fp32
    const float* __restrict__ Whh,     // [4H][H] fp32
    __nv_bfloat16* __restrict__ hshi, __nv_bfloat16* __restrict__ hslo,
    int writeSeq, int writeLast)
{
    __half* sW = (__half*)smem_dyn;                        // 32 x 1032
    __half* sH = sW + 32 * 1032;                           // 4 bufs x 64x136
    float* sG  = (float*)(sH + 4 * 64 * 136);              // ks=0 partials, 64x32
    float* sG2 = sG + 64 * 32;                             // ks=1 partials
    float* sC  = sG2 + 64 * 32;                            // 64 x 8 cell state

    int tid = threadIdx.x, w = tid >> 5, lane = tid & 31;
    int bid = blockIdx.x;
    int jbase = bid * 8;
    unsigned int* mycnt = &g_cnt[(bid >> 4) * 32];

    // load W_hh into SMEM fp16 (once)
    for (int i = tid; i < 32 * 1024; i += 512) {
        int n = i >> 10, k = i & 1023;
        float v = Whh[(size_t)((n >> 3) * H_ + jbase + (n & 7)) * H_ + k];
        sW[n * 1032 + k] = __float2half(v);
    }
    if (tid < 512) sC[tid] = 0.f;

    int rowg = w & 3, colg = (w >> 2) & 1, ks = w >> 3;
    int r0 = rowg * 16;
    int lrA = (lane & 7) + (lane & 8);
    int lcA = (lane & 16) ? 8 : 0;
    uint32_t aB[4], dstB[4];
#pragma unroll
    for (int bf = 0; bf < 4; bf++) {
        aB[bf]  = cvta_s(&sH[bf * 8704 + (r0 + lrA) * 136 + ks * 64 + lcA]);
        dstB[bf] = cvta_s(&sH[bf * 8704]);
    }
    // B bases: two col-tiles (8 gate-cols each) at colg*16 and colg*16+8
    int bRow = (lane & 7);
    int bK   = ((lane >> 3) & 3) * 8;
    uint32_t bW0 = cvta_s(&sW[(colg * 16 + bRow) * 1032 + ks * 64 + bK]);
    uint32_t bW1 = bW0 + (uint32_t)(8 * 1032 * 2);

    // cp.async mapping: 16KB/chunk = 1024 x 16B; 2 per thread
    int pr[2], ps[2];
#pragma unroll
    for (int it = 0; it < 2; it++) {
        int idx = tid + it * 512;
        pr[it] = idx >> 4;            // row 0..63
        ps[it] = (idx & 15) * 8;      // col segment (8 fp16 = 16B)
    }

    int g = lane >> 2, tq = lane & 3;
    int colA = colg * 16 + tq * 2;    // col-tile 0 cols
    int colB = colA + 8;              // col-tile 1 cols
    int bA = r0 + g, bB = bA + 8;
    float* sGx = ks ? sG2 : sG;

    // cell-update thread mapping + xproj addresses
    int cb = tid >> 3, cj = tid & 7;
    const float* xpb = xproj + (size_t)cb * G_ + jbase + cj;

    __syncthreads();

#define PREF(ch, bf) do {                                                     \
    int kc_ = (ch) * 128;                                                     \
    _Pragma("unroll")                                                         \
    for (int it = 0; it < 2; it++) {                                          \
        uint32_t so = (uint32_t)(pr[it] * 136 + ps[it]) * 2u;                 \
        CP_ASYNC16(dstB[(bf)] + so, hr + pr[it] * H_ + kc_ + ps[it]);         \
    }                                                                         \
    CP_COMMIT();                                                              \
} while (0)

    for (int t = 0; t < T_; t++) {
        const __half* hr = g_hf[t & 1];
        unsigned int need = 16u * (unsigned int)t;
        unsigned int vnext = 0u;

        // wait for producers of chunks 0,1; preload chunk 2's counter
        if (tid == 0) {
            while (ld_acq(&g_cnt[0 * 32]) < need) __nanosleep(32);
            while (ld_acq(&g_cnt[1 * 32]) < need) __nanosleep(32);
            vnext = ld_acq(&g_cnt[2 * 32]);
        }
        __syncthreads();
        PREF(0, 0);
        PREF(1, 1);

        // this step's xproj gate values (DRAM latency hidden behind k-loop)
        size_t xt = (size_t)t * B_ * G_;
        float xg0 = xpb[xt];
        float xg1 = xpb[xt + 1 * H_];
        float xg2 = xpb[xt + 2 * H_];
        float xg3 = xpb[xt + 3 * H_];

        float acc[2][4];
#pragma unroll
        for (int ct = 0; ct < 2; ct++)
#pragma unroll
            for (int j = 0; j < 4; j++) acc[ct][j] = 0.f;

        for (int ch = 0; ch < 8; ch++) {
            int cur = ch & 3;
            if (tid == 0 && ch < 6) {
                // check look-ahead value for chunk ch+2 (usually already >= need)
                while (vnext < need) { __nanosleep(32); vnext = ld_acq(&g_cnt[(ch + 2) * 32]); }
                if (ch < 5) vnext = ld_acq(&g_cnt[(ch + 3) * 32]);  // preload next
            }
            if (ch < 7) { CP_WAIT1(); } else { CP_WAIT0(); }
            __syncthreads();
            if (ch < 6) PREF(ch + 2, (ch + 2) & 3);

            int kc = ch * 128;
#pragma unroll
            for (int kg = 0; kg < 2; kg++) {
                uint32_t koff = (uint32_t)(kg * 32) * 2u;
                uint32_t a0[4], a1[4];
                ldsm4(a0, aB[cur] + koff);
                ldsm4(a1, aB[cur] + koff + 32);
                uint32_t bo = (uint32_t)(kc + kg * 32) * 2u;
                uint32_t bh[4], bh1[4];
                ldsm4(bh, bW0 + bo);
                ldsm4(bh1, bW1 + bo);
                mma16816h(acc[0], a0, bh);
                mma16816h(acc[0], a1, bh + 2);
                mma16816h(acc[1], a0, bh1);
                mma16816h(acc[1], a1, bh1 + 2);
            }
        }

        // partial gate sums -> sG (ks=0) / sG2 (ks=1)
        {
            *(float2*)&sGx[bA * 32 + colA] = make_float2(acc[0][0], acc[0][1]);
            *(float2*)&sGx[bB * 32 + colA] = make_float2(acc[0][2], acc[0][3]);
            *(float2*)&sGx[bA * 32 + colB] = make_float2(acc[1][0], acc[1][1]);
            *(float2*)&sGx[bB * 32 + colB] = make_float2(acc[1][2], acc[1][3]);
        }
        __syncthreads();

        // cell update: 512 cells/block, 1 per thread
        __half* hw = g_hf[(t + 1) & 1];
        {
            float iv = sG[cb * 32 + cj]      + sG2[cb * 32 + cj]      + xg0;
            float fv = sG[cb * 32 + 8 + cj]  + sG2[cb * 32 + 8 + cj]  + xg1;
            float gv = sG[cb * 32 + 16 + cj] + sG2[cb * 32 + 16 + cj] + xg2;
            float ov = sG[cb * 32 + 24 + cj] + sG2[cb * 32 + 24 + cj] + xg3;
            float ig = 1.f / (1.f + expf(-iv));
            float fg = 1.f / (1.f + expf(-fv));
            float gg = tanhf(gv);
            float og = 1.f / (1.f + expf(-ov));
            float cc = fg * sC[cb * 8 + cj] + ig * gg;
            sC[cb * 8 + cj] = cc;
            float hh = og * tanhf(cc);
            int hidx = cb * H_ + jbase + cj;
            hw[hidx] = __float2half(hh);
            if (writeSeq) {
                __nv_bfloat16 hb = __float2bfloat16(hh);
                size_t sidx = ((size_t)t * B_ + cb) * H_ + jbase + cj;
                hshi[sidx] = hb;
                hslo[sidx] = __float2bfloat16(hh - __bfloat162float(hb));
            }
            if (writeLast && t == T_ - 1) g_hlast[hidx] = hh;
        }
        // publish: h for step t+1 from this block is ready
        __threadfence();
        __syncthreads();
        if (tid == 0) atomicAdd(mycnt, 1u);
    }
#undef PREF
}

// ---------------- FC head ----------------
__global__ __launch_bounds__(256) void fc_kernel(
    const float* __restrict__ fc_w, const float* __restrict__ fc_b,
    float* __restrict__ out)
{
    __shared__ float sh[H_];
    int b = blockIdx.x, tid = threadIdx.x;
    const float* hlast = g_hlast + (size_t)b * H_;
    for (int i = tid; i < H_; i += 256) sh[i] = hlast[i];
    __syncthreads();
    int o = tid;
    const float* wrow = fc_w + (size_t)o * H_;
    float acc = fc_b[o];
#pragma unroll 8
    for (int k = 0; k < H_; k++) acc += sh[k] * wrow[k];
    out[b * O_ + o] = acc;
}

// ---------------- launch ----------------
// W: 32*1032 fp16 + h: 4*64*136 fp16 + sG/sG2: 2*2048 f32 + sC: 512 f32
#define SMEM_REC ((32*1032 + 4*64*136) * 2 + (2*64*32 + 64*8) * 4)

extern "C" void kernel_launch(void* const* d_in, const int* in_sizes, int n_in,
                              void* d_out, int out_size) {
    (void)in_sizes; (void)n_in; (void)out_size;
    const float* x     = (const float*)d_in[0];
    const float* W_ih0 = (const float*)d_in[1];
    const float* W_hh0 = (const float*)d_in[2];
    const float* b_ih0 = (const float*)d_in[3];
    const float* b_hh0 = (const float*)d_in[4];
    const float* W_ih1 = (const float*)d_in[5];
    const float* W_hh1 = (const float*)d_in[6];
    const float* b_ih1 = (const float*)d_in[7];
    const float* b_hh1 = (const float*)d_in[8];
    const float* fc_w  = (const float*)d_in[9];
    const float* fc_b  = (const float*)d_in[10];
    float* out = (float*)d_out;

    float *xp0, *xp1;
    __nv_bfloat16 *xhi, *xlo, *w0hi, *w0lo, *w1hi, *w1lo, *hs0hi, *hs0lo;
    cudaGetSymbolAddress((void**)&xp0, g_xproj0);
    cudaGetSymbolAddress((void**)&xp1, g_xproj1);
    cudaGetSymbolAddress((void**)&xhi, g_xhi);
    cudaGetSymbolAddress((void**)&xlo, g_xlo);
    cudaGetSymbolAddress((void**)&w0hi, g_wih0hi);
    cudaGetSymbolAddress((void**)&w0lo, g_wih0lo);
    cudaGetSymbolAddress((void**)&w1hi, g_wih1hi);
    cudaGetSymbolAddress((void**)&w1lo, g_wih1lo);
    cudaGetSymbolAddress((void**)&hs0hi, g_hs0hi);
    cudaGetSymbolAddress((void**)&hs0lo, g_hs0lo);

    cudaFuncSetAttribute(lstm_recur_mma,
        cudaFuncAttributeMaxDynamicSharedMemorySize, SMEM_REC);

    // splits (projection operands, bf16 3-term)
    int nx4 = B_ * T_ * I_ / 4;
    split_kernel<<<(nx4 + 255) / 256, 256>>>(x, xhi, xlo, nx4);
    int nw04 = G_ * I_ / 4;
    split_kernel<<<(nw04 + 255) / 256, 256>>>(W_ih0, w0hi, w0lo, nw04);
    int nw14 = G_ * H_ / 4;
    split_kernel<<<(nw14 + 255) / 256, 256>>>(W_ih1, w1hi, w1lo, nw14);

    dim3 pgrid(G_ / 64, (B_ * T_) / 128);

    // layer 0
    mma_xproj<<<pgrid, 256>>>(xhi, xlo, w0hi, w0lo, b_ih0, b_hh0, xp0, I_, 0);
    init_kernel<<<64, 256>>>();
    lstm_recur_mma<<<128, 512, SMEM_REC>>>(xp0, W_hh0, hs0hi, hs0lo, 1, 0);

    // layer 1
    mma_xproj<<<pgrid, 256>>>(hs0hi, hs0lo, w1hi, w1lo, b_ih1, b_hh1, xp1, H_, 1);
    init_kernel<<<64, 256>>>();
    lstm_recur_mma<<<128, 512, SMEM_REC>>>(xp1, W_hh1, hs0hi, hs0lo, 0, 1);

    // head
    fc_kernel<<<64, 256>>>(fc_w, fc_b, out);
}

// round 12
// speedup vs baseline: 1.2178x; 1.2178x over previous
#include <cuda_runtime.h>
#include <cuda_bf16.h>
#include <cuda_fp16.h>
#include <stdint.h>
#include <math.h>

#define B_ 64
#define T_ 512
#define I_ 256
#define H_ 1024
#define G_ 4096
#define O_ 256

// ---------------- device scratch ----------------
__device__ float g_xproj0[(size_t)T_ * B_ * G_];   // [t][b][4H] fp32
__device__ float g_xproj1[(size_t)T_ * B_ * G_];
__device__ __nv_bfloat16 g_xhi[(size_t)B_ * T_ * I_];
__device__ __nv_bfloat16 g_xlo[(size_t)B_ * T_ * I_];
__device__ __nv_bfloat16 g_wih0hi[(size_t)G_ * I_];
__device__ __nv_bfloat16 g_wih0lo[(size_t)G_ * I_];
__device__ __nv_bfloat16 g_wih1hi[(size_t)G_ * H_];
__device__ __nv_bfloat16 g_wih1lo[(size_t)G_ * H_];
__device__ __nv_bfloat16 g_hs0hi[(size_t)T_ * B_ * H_];  // layer-0 outputs hi/lo (for proj)
__device__ __nv_bfloat16 g_hs0lo[(size_t)T_ * B_ * H_];
__device__ __half g_hf[2][B_ * H_];                // recurrent h, single fp16
__device__ float g_hlast[B_ * H_];                 // fp32 final h for FC
__device__ unsigned int g_cnt[8 * 32];             // 8 group counters, 128B padded
__device__ unsigned int g_super;                   // super counter (8 arrivals/step)

// ---------------- helpers ----------------
__device__ __forceinline__ void ldsm4(uint32_t* r, uint32_t addr) {
    asm volatile("ldmatrix.sync.aligned.m8n8.x4.shared.b16 {%0,%1,%2,%3}, [%4];"
        : "=r"(r[0]), "=r"(r[1]), "=r"(r[2]), "=r"(r[3]) : "r"(addr));
}
__device__ __forceinline__ void ldsm2(uint32_t* r, uint32_t addr) {
    asm volatile("ldmatrix.sync.aligned.m8n8.x2.shared.b16 {%0,%1}, [%2];"
        : "=r"(r[0]), "=r"(r[1]) : "r"(addr));
}
// bf16 mma (projections)
__device__ __forceinline__ void mma16816(float* c, const uint32_t* a, const uint32_t* b) {
    asm volatile("mma.sync.aligned.m16n8k16.row.col.f32.bf16.bf16.f32 "
        "{%0,%1,%2,%3}, {%4,%5,%6,%7}, {%8,%9}, {%0,%1,%2,%3};"
        : "+f"(c[0]), "+f"(c[1]), "+f"(c[2]), "+f"(c[3])
        : "r"(a[0]), "r"(a[1]), "r"(a[2]), "r"(a[3]), "r"(b[0]), "r"(b[1]));
}
// fp16 mma (recurrence)
__device__ __forceinline__ void mma16816h(float* c, const uint32_t* a, const uint32_t* b) {
    asm volatile("mma.sync.aligned.m16n8k16.row.col.f32.f16.f16.f32 "
        "{%0,%1,%2,%3}, {%4,%5,%6,%7}, {%8,%9}, {%0,%1,%2,%3};"
        : "+f"(c[0]), "+f"(c[1]), "+f"(c[2]), "+f"(c[3])
        : "r"(a[0]), "r"(a[1]), "r"(a[2]), "r"(a[3]), "r"(b[0]), "r"(b[1]));
}
__device__ __forceinline__ uint32_t cvta_s(const void* p) {
    return (uint32_t)__cvta_generic_to_shared(p);
}
__device__ __forceinline__ unsigned int ld_acq(const unsigned int* p) {
    unsigned int v;
    asm volatile("ld.acquire.gpu.u32 %0, [%1];" : "=r"(v) : "l"(p) : "memory");
    return v;
}
// fast activations (inf-safe)
__device__ __forceinline__ float fsigmoid(float x) {
    return __fdividef(1.f, 1.f + __expf(-x));
}
__device__ __forceinline__ float ftanh(float x) {
    return 1.f - __fdividef(2.f, 1.f + __expf(2.f * x));
}
#define CP_ASYNC16(d, s) asm volatile("cp.async.cg.shared.global [%0], [%1], 16;" :: "r"(d), "l"(s))
#define CP_COMMIT()      asm volatile("cp.async.commit_group;" ::: "memory")
#define CP_WAIT0()       asm volatile("cp.async.wait_group 0;" ::: "memory")

// ---------------- init ----------------
__global__ void init_kernel() {
    int idx = blockIdx.x * blockDim.x + threadIdx.x;
    if (idx < 8 * 32) g_cnt[idx] = 0u;
    if (idx == 0) g_super = 0u;
    __half z = __float2half(0.f);
    int n = 2 * B_ * H_;
    __half* ph = (__half*)g_hf;
    for (int i = idx; i < n; i += gridDim.x * blockDim.x) ph[i] = z;
}

// ---------------- fp32 -> bf16 hi/lo split (projection operands) ------------
__global__ void split_kernel(const float* __restrict__ src,
                             __nv_bfloat16* __restrict__ hi,
                             __nv_bfloat16* __restrict__ lo, int n4) {
    int i = blockIdx.x * blockDim.x + threadIdx.x;
    if (i >= n4) return;
    float4 v = ((const float4*)src)[i];
    __nv_bfloat16 h0 = __float2bfloat16(v.x);
    __nv_bfloat16 h1 = __float2bfloat16(v.y);
    __nv_bfloat16 h2 = __float2bfloat16(v.z);
    __nv_bfloat16 h3 = __float2bfloat16(v.w);
    __nv_bfloat162 a, b;
    a.x = h0; a.y = h1; b.x = h2; b.y = h3;
    ((__nv_bfloat162*)hi)[2 * i] = a;
    ((__nv_bfloat162*)hi)[2 * i + 1] = b;
    a.x = __float2bfloat16(v.x - __bfloat162float(h0));
    a.y = __float2bfloat16(v.y - __bfloat162float(h1));
    b.x = __float2bfloat16(v.z - __bfloat162float(h2));
    b.y = __float2bfloat16(v.w - __bfloat162float(h3));
    ((__nv_bfloat162*)lo)[2 * i] = a;
    ((__nv_bfloat162*)lo)[2 * i + 1] = b;
}

// ---------------- hierarchical grid barrier (128 blocks, 8 groups of 16) ----
__device__ __forceinline__ void gridbar2(int t, int bid) {
    __threadfence();
    __syncthreads();
    if (threadIdx.x == 0) {
        unsigned int r = atomicAdd(&g_cnt[(bid >> 4) * 32], 1u);
        if ((r & 15u) == 15u) atomicAdd(&g_super, 1u);
        unsigned int tgt = 8u * (unsigned int)(t + 1);
        while (ld_acq(&g_super) < tgt) __nanosleep(32);
    }
    __syncthreads();
}

// ---------------- split-bf16 MMA projection GEMM (cp.async 2-stage) ---------
#define P_ASZ (128 * 40)
#define P_BSZ (64 * 40)
#define P_BUF (2 * P_ASZ + 2 * P_BSZ)
__global__ __launch_bounds__(256) void mma_xproj(
    const __nv_bfloat16* __restrict__ Ahi, const __nv_bfloat16* __restrict__ Alo,
    const __nv_bfloat16* __restrict__ Whi, const __nv_bfloat16* __restrict__ Wlo,
    const float* __restrict__ b1, const float* __restrict__ b2,
    float* __restrict__ Cout, int K, int mode)
{
    extern __shared__ __nv_bfloat16 psm[];
    __shared__ float sBias[64];

    int tid = threadIdx.x;
    int n0 = blockIdx.x * 64;
    int m0 = blockIdx.y * 128;
    int w = tid >> 5, lane = tid & 31;
    int r0 = w * 16;

    if (tid < 64) sBias[tid] = b1[n0 + tid] + b2[n0 + tid];

    float acc[8][4];
#pragma unroll
    for (int i = 0; i < 8; i++)
#pragma unroll
        for (int j = 0; j < 4; j++) acc[i][j] = 0.f;

    size_t arow[2]; int aoff[2];
#pragma unroll
    for (int it = 0; it < 2; it++) {
        int idx = tid + it * 256;
        int r = idx >> 2, seg = idx & 3;
        int m = m0 + r;
        arow[it] = (mode == 0) ? ((size_t)(m & 63) * T_ + (size_t)(m >> 6)) * (size_t)K + (size_t)(seg * 8)
                               : (size_t)m * (size_t)K + (size_t)(seg * 8);
        aoff[it] = r * 40 + seg * 8;
    }
    int br = tid >> 2, bseg = tid & 3;
    size_t brow = (size_t)(n0 + br) * (size_t)K + (size_t)(bseg * 8);
    int boff = br * 40 + bseg * 8;

    int lrA = (lane & 7) + (lane & 8);
    int lcA = (lane & 16) ? 8 : 0;
    int lrB = lane & 7;
    int lcB = (lane & 8) ? 8 : 0;

    uint32_t dAhi[2], dAlo[2], dBhi[2], dBlo[2];
    uint32_t aHiB[2], aLoB[2], bHiB[2], bLoB[2];
#pragma unroll
    for (int buf = 0; buf < 2; buf++) {
        uint32_t base = cvta_s(psm + buf * P_BUF);
        dAhi[buf] = base;
        dAlo[buf] = base + P_ASZ * 2;
        dBhi[buf] = base + 2 * P_ASZ * 2;
        dBlo[buf] = base + (2 * P_ASZ + P_BSZ) * 2;
        aHiB[buf] = dAhi[buf] + (uint32_t)(((r0 + lrA) * 40 + lcA) * 2);
        aLoB[buf] = dAlo[buf] + (uint32_t)(((r0 + lrA) * 40 + lcA) * 2);
        bHiB[buf] = dBhi[buf] + (uint32_t)((lrB * 40 + lcB) * 2);
        bLoB[buf] = dBlo[buf] + (uint32_t)((lrB * 40 + lcB) * 2);
    }

#define PREFP(kc, buf) do {                                                   \
    _Pragma("unroll")                                                         \
    for (int it = 0; it < 2; it++) {                                          \
        CP_ASYNC16(dAhi[(buf)] + (uint32_t)(aoff[it] * 2), Ahi + arow[it] + (kc)); \
        CP_ASYNC16(dAlo[(buf)] + (uint32_t)(aoff[it] * 2), Alo + arow[it] + (kc)); \
    }                                                                         \
    CP_ASYNC16(dBhi[(buf)] + (uint32_t)(boff * 2), Whi + brow + (kc));        \
    CP_ASYNC16(dBlo[(buf)] + (uint32_t)(boff * 2), Wlo + brow + (kc));        \
    CP_COMMIT();                                                              \
} while (0)

    PREFP(0, 0);

    for (int kc = 0; kc < K; kc += 32) {
        int buf = (kc >> 5) & 1;
        CP_WAIT0();
        __syncthreads();
        if (kc + 32 < K) PREFP(kc + 32, buf ^ 1);
#pragma unroll
        for (int ks = 0; ks < 2; ks++) {
            int k0 = ks * 16;
            uint32_t ah[4], al[4];
            ldsm4(ah, aHiB[buf] + (uint32_t)(k0 * 2));
            ldsm4(al, aLoB[buf] + (uint32_t)(k0 * 2));
#pragma unroll
            for (int nt = 0; nt < 8; nt++) {
                uint32_t bh[2], bl[2];
                uint32_t off = (uint32_t)(nt * 8 * 40 + k0) * 2u;
                ldsm2(bh, bHiB[buf] + off);
                ldsm2(bl, bLoB[buf] + off);
                mma16816(acc[nt], ah, bh);
                mma16816(acc[nt], ah, bl);
                mma16816(acc[nt], al, bh);
            }
        }
        __syncthreads();
    }
#undef PREFP

    int g = lane >> 2, tq = lane & 3;
#pragma unroll
    for (int nt = 0; nt < 8; nt++) {
        int col = nt * 8 + tq * 2;
        float bb0 = sBias[col], bb1 = sBias[col + 1];
        size_t mA = (size_t)(m0 + r0 + g) * G_ + n0 + col;
        size_t mB = (size_t)(m0 + r0 + g + 8) * G_ + n0 + col;
        float2 v0 = make_float2(acc[nt][0] + bb0, acc[nt][1] + bb1);
        float2 v1 = make_float2(acc[nt][2] + bb0, acc[nt][3] + bb1);
        *(float2*)&Cout[mA] = v0;
        *(float2*)&Cout[mB] = v1;
    }
}
#define SMEM_PROJ (P_BUF * 2 * 2)

// ---------------- persistent LSTM recurrence: fp16, 256-col chunks ----------
// 128 blocks x 512 threads. Warp w: rowg=w&3, colg=(w>>2)&1, ks=w>>3 (k-half
// of each 256-col chunk). Block owns 8 h-cols (32 gate-cols). W_hh fp16 in
// SMEM; h fp16, 2-buffer cp.async, 4 chunks/step; hierarchical grid barrier.
extern __shared__ char smem_dyn[];
__global__ __launch_bounds__(512) void lstm_recur_mma(
    const float* __restrict__ xproj,   // [T][B][4H] fp32
    const float* __restrict__ Whh,     // [4H][H] fp32
    __nv_bfloat16* __restrict__ hshi, __nv_bfloat16* __restrict__ hslo,
    int writeSeq, int writeLast)
{
    __half* sW = (__half*)smem_dyn;                        // 32 x 1032
    __half* sH = sW + 32 * 1032;                           // 2 bufs x 64x264
    float* sG  = (float*)(sH + 2 * 64 * 264);              // ks=0 partials, 64x32
    float* sG2 = sG + 64 * 32;                             // ks=1 partials
    float* sC  = sG2 + 64 * 32;                            // 64 x 8 cell state

    int tid = threadIdx.x, w = tid >> 5, lane = tid & 31;
    int bid = blockIdx.x;
    int jbase = bid * 8;

    // load W_hh into SMEM fp16 (once)
    for (int i = tid; i < 32 * 1024; i += 512) {
        int n = i >> 10, k = i & 1023;
        float v = Whh[(size_t)((n >> 3) * H_ + jbase + (n & 7)) * H_ + k];
        sW[n * 1032 + k] = __float2half(v);
    }
    if (tid < 512) sC[tid] = 0.f;

    int rowg = w & 3, colg = (w >> 2) & 1, ks = w >> 3;
    int r0 = rowg * 16;
    int lrA = (lane & 7) + (lane & 8);
    int lcA = (lane & 16) ? 8 : 0;
    uint32_t aB[2], dstB[2];
#pragma unroll
    for (int bf = 0; bf < 2; bf++) {
        aB[bf]  = cvta_s(&sH[bf * 16896 + (r0 + lrA) * 264 + ks * 128 + lcA]);
        dstB[bf] = cvta_s(&sH[bf * 16896]);
    }
    // B bases: two col-tiles (8 gate-cols each) at colg*16 and colg*16+8
    int bRow = (lane & 7);
    int bK   = ((lane >> 3) & 3) * 8;
    uint32_t bW0 = cvta_s(&sW[(colg * 16 + bRow) * 1032 + ks * 128 + bK]);
    uint32_t bW1 = bW0 + (uint32_t)(8 * 1032 * 2);

    // cp.async mapping: 32KB/chunk = 2048 x 16B; 4 per thread
    int pr[4], ps[4];
#pragma unroll
    for (int it = 0; it < 4; it++) {
        int idx = tid + it * 512;
        pr[it] = idx >> 5;            // row 0..63
        ps[it] = (idx & 31) * 8;      // col segment (8 fp16 = 16B) within 256
    }

    int g = lane >> 2, tq = lane & 3;
    int colA = colg * 16 + tq * 2;    // col-tile 0 cols
    int colB = colA + 8;              // col-tile 1 cols
    int bA = r0 + g, bB = bA + 8;
    float* sGx = ks ? sG2 : sG;

    // cell-update thread mapping + xproj addresses
    int cb = tid >> 3, cj = tid & 7;
    const float* xpb = xproj + (size_t)cb * G_ + jbase + cj;

    __syncthreads();

#define PREF(ch, bf) do {                                                     \
    int kc_ = (ch) * 256;                                                     \
    _Pragma("unroll")                                                         \
    for (int it = 0; it < 4; it++) {                                          \
        uint32_t so = (uint32_t)(pr[it] * 264 + ps[it]) * 2u;                 \
        CP_ASYNC16(dstB[(bf)] + so, hr + pr[it] * H_ + kc_ + ps[it]);         \
    }                                                                         \
    CP_COMMIT();                                                              \
} while (0)

    for (int t = 0; t < T_; t++) {
        const __half* hr = g_hf[t & 1];

        PREF(0, 0);

        // this step's xproj gate values (DRAM latency hidden behind k-loop)
        size_t xt = (size_t)t * B_ * G_;
        float xg0 = xpb[xt];
        float xg1 = xpb[xt + 1 * H_];
        float xg2 = xpb[xt + 2 * H_];
        float xg3 = xpb[xt + 3 * H_];

        float acc[2][4];
#pragma unroll
        for (int ct = 0; ct < 2; ct++)
#pragma unroll
            for (int j = 0; j < 4; j++) acc[ct][j] = 0.f;

        for (int ch = 0; ch < 4; ch++) {
            int cur = ch & 1;
            CP_WAIT0();
            __syncthreads();
            if (ch < 3) PREF(ch + 1, cur ^ 1);

            int kc = ch * 256;
#pragma unroll
            for (int kg = 0; kg < 4; kg++) {
                uint32_t koff = (uint32_t)(kg * 32) * 2u;
                uint32_t a0[4], a1[4];
                ldsm4(a0, aB[cur] + koff);
                ldsm4(a1, aB[cur] + koff + 32);
                uint32_t bo = (uint32_t)(kc + kg * 32) * 2u;
                uint32_t bh[4], bh1[4];
                ldsm4(bh, bW0 + bo);
                ldsm4(bh1, bW1 + bo);
                mma16816h(acc[0], a0, bh);
                mma16816h(acc[0], a1, bh + 2);
                mma16816h(acc[1], a0, bh1);
                mma16816h(acc[1], a1, bh1 + 2);
            }
            __syncthreads();
        }

        // partial gate sums -> sG (ks=0) / sG2 (ks=1)
        {
            *(float2*)&sGx[bA * 32 + colA] = make_float2(acc[0][0], acc[0][1]);
            *(float2*)&sGx[bB * 32 + colA] = make_float2(acc[0][2], acc[0][3]);
            *(float2*)&sGx[bA * 32 + colB] = make_float2(acc[1][0], acc[1][1]);
            *(float2*)&sGx[bB * 32 + colB] = make_float2(acc[1][2], acc[1][3]);
        }
        __syncthreads();

        // cell update: 512 cells/block, 1 per thread
        __half* hw = g_hf[(t + 1) & 1];
        {
            float iv = sG[cb * 32 + cj]      + sG2[cb * 32 + cj]      + xg0;
            float fv = sG[cb * 32 + 8 + cj]  + sG2[cb * 32 + 8 + cj]  + xg1;
            float gv = sG[cb * 32 + 16 + cj] + sG2[cb * 32 + 16 + cj] + xg2;
            float ov = sG[cb * 32 + 24 + cj] + sG2[cb * 32 + 24 + cj] + xg3;
            float ig = fsigmoid(iv);
            float fg = fsigmoid(fv);
            float gg = ftanh(gv);
            float og = fsigmoid(ov);
            float cc = fg * sC[cb * 8 + cj] + ig * gg;
            sC[cb * 8 + cj] = cc;
            float hh = og * ftanh(cc);
            int hidx = cb * H_ + jbase + cj;
            hw[hidx] = __float2half(hh);
            if (writeSeq) {
                __nv_bfloat16 hb = __float2bfloat16(hh);
                size_t sidx = ((size_t)t * B_ + cb) * H_ + jbase + cj;
                hshi[sidx] = hb;
                hslo[sidx] = __float2bfloat16(hh - __bfloat162float(hb));
            }
            if (writeLast && t == T_ - 1) g_hlast[hidx] = hh;
        }
        if (t < T_ - 1) gridbar2(t, bid);   // last step: kernel boundary syncs
    }
#undef PREF
}

// ---------------- FC head ----------------
__global__ __launch_bounds__(256) void fc_kernel(
    const float* __restrict__ fc_w, const float* __restrict__ fc_b,
    float* __restrict__ out)
{
    __shared__ float sh[H_];
    int b = blockIdx.x, tid = threadIdx.x;
    const float* hlast = g_hlast + (size_t)b * H_;
    for (int i = tid; i < H_; i += 256) sh[i] = hlast[i];
    __syncthreads();
    int o = tid;
    const float* wrow = fc_w + (size_t)o * H_;
    float acc = fc_b[o];
#pragma unroll 8
    for (int k = 0; k < H_; k++) acc += sh[k] * wrow[k];
    out[b * O_ + o] = acc;
}

// ---------------- launch ----------------
// W: 32*1032 fp16 + h: 2*64*264 fp16 + sG/sG2: 2*2048 f32 + sC: 512 f32
#define SMEM_REC ((32*1032 + 2*64*264) * 2 + (2*64*32 + 64*8) * 4)

extern "C" void kernel_launch(void* const* d_in, const int* in_sizes, int n_in,
                              void* d_out, int out_size) {
    (void)in_sizes; (void)n_in; (void)out_size;
    const float* x     = (const float*)d_in[0];
    const float* W_ih0 = (const float*)d_in[1];
    const float* W_hh0 = (const float*)d_in[2];
    const float* b_ih0 = (const float*)d_in[3];
    const float* b_hh0 = (const float*)d_in[4];
    const float* W_ih1 = (const float*)d_in[5];
    const float* W_hh1 = (const float*)d_in[6];
    const float* b_ih1 = (const float*)d_in[7];
    const float* b_hh1 = (const float*)d_in[8];
    const float* fc_w  = (const float*)d_in[9];
    const float* fc_b  = (const float*)d_in[10];
    float* out = (float*)d_out;

    float *xp0, *xp1;
    __nv_bfloat16 *xhi, *xlo, *w0hi, *w0lo, *w1hi, *w1lo, *hs0hi, *hs0lo;
    cudaGetSymbolAddress((void**)&xp0, g_xproj0);
    cudaGetSymbolAddress((void**)&xp1, g_xproj1);
    cudaGetSymbolAddress((void**)&xhi, g_xhi);
    cudaGetSymbolAddress((void**)&xlo, g_xlo);
    cudaGetSymbolAddress((void**)&w0hi, g_wih0hi);
    cudaGetSymbolAddress((void**)&w0lo, g_wih0lo);
    cudaGetSymbolAddress((void**)&w1hi, g_wih1hi);
    cudaGetSymbolAddress((void**)&w1lo, g_wih1lo);
    cudaGetSymbolAddress((void**)&hs0hi, g_hs0hi);
    cudaGetSymbolAddress((void**)&hs0lo, g_hs0lo);

    cudaFuncSetAttribute(lstm_recur_mma,
        cudaFuncAttributeMaxDynamicSharedMemorySize, SMEM_REC);
    cudaFuncSetAttribute(mma_xproj,
        cudaFuncAttributeMaxDynamicSharedMemorySize, SMEM_PROJ);

    // splits (projection operands, bf16 3-term)
    int nx4 = B_ * T_ * I_ / 4;
    split_kernel<<<(nx4 + 255) / 256, 256>>>(x, xhi, xlo, nx4);
    int nw04 = G_ * I_ / 4;
    split_kernel<<<(nw04 + 255) / 256, 256>>>(W_ih0, w0hi, w0lo, nw04);
    int nw14 = G_ * H_ / 4;
    split_kernel<<<(nw14 + 255) / 256, 256>>>(W_ih1, w1hi, w1lo, nw14);

    dim3 pgrid(G_ / 64, (B_ * T_) / 128);

    // layer 0
    mma_xproj<<<pgrid, 256, SMEM_PROJ>>>(xhi, xlo, w0hi, w0lo, b_ih0, b_hh0, xp0, I_, 0);
    init_kernel<<<64, 256>>>();
    lstm_recur_mma<<<128, 512, SMEM_REC>>>(xp0, W_hh0, hs0hi, hs0lo, 1, 0);

    // layer 1
    mma_xproj<<<pgrid, 256, SMEM_PROJ>>>(hs0hi, hs0lo, w1hi, w1lo, b_ih1, b_hh1, xp1, H_, 1);
    init_kernel<<<64, 256>>>();
    lstm_recur_mma<<<128, 512, SMEM_REC>>>(xp1, W_hh1, hs0hi, hs0lo, 0, 1);

    // head
    fc_kernel<<<64, 256>>>(fc_w, fc_b, out);
}

// round 13
// speedup vs baseline: 1.5893x; 1.3050x over previous
#include <cuda_runtime.h>
#include <cuda_bf16.h>
#include <cuda_fp16.h>
#include <stdint.h>
#include <math.h>

#define B_ 64
#define T_ 512
#define I_ 256
#define H_ 1024
#define G_ 4096
#define O_ 256

// ---------------- device scratch ----------------
__device__ float g_xproj0[(size_t)T_ * B_ * G_];   // [t][b][4H] fp32 (layer0 input proj)
__device__ __nv_bfloat16 g_xhi[(size_t)B_ * T_ * I_];
__device__ __nv_bfloat16 g_xlo[(size_t)B_ * T_ * I_];
__device__ __nv_bfloat16 g_wih0hi[(size_t)G_ * I_];
__device__ __nv_bfloat16 g_wih0lo[(size_t)G_ * I_];
__device__ __half g_wi1h[(size_t)G_ * H_];         // W_ih1 fp16 [4H][H]
__device__ __half g_wh1h[(size_t)G_ * H_];         // W_hh1 fp16 [4H][H]
__device__ __half g_h0[2][B_ * H_];                // layer0 h, fp16, double buffer
__device__ __half g_h1[2][B_ * H_];                // layer1 h
__device__ float g_hlast[B_ * H_];                 // fp32 final h1 for FC
__device__ unsigned int g_cnt[8 * 32];             // 8 group counters, 128B padded
__device__ unsigned int g_super;

// ---------------- helpers ----------------
__device__ __forceinline__ void ldsm4(uint32_t* r, uint32_t addr) {
    asm volatile("ldmatrix.sync.aligned.m8n8.x4.shared.b16 {%0,%1,%2,%3}, [%4];"
        : "=r"(r[0]), "=r"(r[1]), "=r"(r[2]), "=r"(r[3]) : "r"(addr));
}
__device__ __forceinline__ void ldsm2(uint32_t* r, uint32_t addr) {
    asm volatile("ldmatrix.sync.aligned.m8n8.x2.shared.b16 {%0,%1}, [%2];"
        : "=r"(r[0]), "=r"(r[1]) : "r"(addr));
}
__device__ __forceinline__ void mma16816(float* c, const uint32_t* a, const uint32_t* b) {
    asm volatile("mma.sync.aligned.m16n8k16.row.col.f32.bf16.bf16.f32 "
        "{%0,%1,%2,%3}, {%4,%5,%6,%7}, {%8,%9}, {%0,%1,%2,%3};"
        : "+f"(c[0]), "+f"(c[1]), "+f"(c[2]), "+f"(c[3])
        : "r"(a[0]), "r"(a[1]), "r"(a[2]), "r"(a[3]), "r"(b[0]), "r"(b[1]));
}
__device__ __forceinline__ void mma16816h(float* c, const uint32_t* a, const uint32_t* b) {
    asm volatile("mma.sync.aligned.m16n8k16.row.col.f32.f16.f16.f32 "
        "{%0,%1,%2,%3}, {%4,%5,%6,%7}, {%8,%9}, {%0,%1,%2,%3};"
        : "+f"(c[0]), "+f"(c[1]), "+f"(c[2]), "+f"(c[3])
        : "r"(a[0]), "r"(a[1]), "r"(a[2]), "r"(a[3]), "r"(b[0]), "r"(b[1]));
}
__device__ __forceinline__ uint32_t cvta_s(const void* p) {
    return (uint32_t)__cvta_generic_to_shared(p);
}
__device__ __forceinline__ unsigned int ld_acq(const unsigned int* p) {
    unsigned int v;
    asm volatile("ld.acquire.gpu.u32 %0, [%1];" : "=r"(v) : "l"(p) : "memory");
    return v;
}
__device__ __forceinline__ float fsigmoid(float x) {
    return __fdividef(1.f, 1.f + __expf(-x));
}
__device__ __forceinline__ float ftanh(float x) {
    return 1.f - __fdividef(2.f, 1.f + __expf(2.f * x));
}
#define CP_ASYNC16(d, s) asm volatile("cp.async.cg.shared.global [%0], [%1], 16;" :: "r"(d), "l"(s))
#define CP_COMMIT()      asm volatile("cp.async.commit_group;" ::: "memory")
#define CP_WAIT0()       asm volatile("cp.async.wait_group 0;" ::: "memory")

// ---------------- init ----------------
__global__ void init_kernel() {
    int idx = blockIdx.x * blockDim.x + threadIdx.x;
    if (idx < 8 * 32) g_cnt[idx] = 0u;
    if (idx == 0) g_super = 0u;
    __half z = __float2half(0.f);
    int n = 2 * B_ * H_;
    __half* p0 = (__half*)g_h0;
    __half* p1 = (__half*)g_h1;
    for (int i = idx; i < n; i += gridDim.x * blockDim.x) { p0[i] = z; p1[i] = z; }
}

// ---------------- fp32 -> bf16 hi/lo split ----------------
__global__ void split_kernel(const float* __restrict__ src,
                             __nv_bfloat16* __restrict__ hi,
                             __nv_bfloat16* __restrict__ lo, int n4) {
    int i = blockIdx.x * blockDim.x + threadIdx.x;
    if (i >= n4) return;
    float4 v = ((const float4*)src)[i];
    __nv_bfloat16 h0 = __float2bfloat16(v.x);
    __nv_bfloat16 h1 = __float2bfloat16(v.y);
    __nv_bfloat16 h2 = __float2bfloat16(v.z);
    __nv_bfloat16 h3 = __float2bfloat16(v.w);
    __nv_bfloat162 a, b;
    a.x = h0; a.y = h1; b.x = h2; b.y = h3;
    ((__nv_bfloat162*)hi)[2 * i] = a;
    ((__nv_bfloat162*)hi)[2 * i + 1] = b;
    a.x = __float2bfloat16(v.x - __bfloat162float(h0));
    a.y = __float2bfloat16(v.y - __bfloat162float(h1));
    b.x = __float2bfloat16(v.z - __bfloat162float(h2));
    b.y = __float2bfloat16(v.w - __bfloat162float(h3));
    ((__nv_bfloat162*)lo)[2 * i] = a;
    ((__nv_bfloat162*)lo)[2 * i + 1] = b;
}

// ---------------- fp32 -> fp16 convert ----------------
__global__ void conv_half(const float* __restrict__ src, __half* __restrict__ dst, int n4) {
    int i = blockIdx.x * blockDim.x + threadIdx.x;
    if (i >= n4) return;
    float4 v = ((const float4*)src)[i];
    __half2 a, b;
    a.x = __float2half(v.x); a.y = __float2half(v.y);
    b.x = __float2half(v.z); b.y = __float2half(v.w);
    ((__half2*)dst)[2 * i] = a;
    ((__half2*)dst)[2 * i + 1] = b;
}

// ---------------- hierarchical grid barrier ----------------
__device__ __forceinline__ void gridbar2(int t, int bid) {
    __threadfence();
    __syncthreads();
    if (threadIdx.x == 0) {
        unsigned int r = atomicAdd(&g_cnt[(bid >> 4) * 32], 1u);
        if ((r & 15u) == 15u) atomicAdd(&g_super, 1u);
        unsigned int tgt = 8u * (unsigned int)(t + 1);
        while (ld_acq(&g_super) < tgt) __nanosleep(32);
    }
    __syncthreads();
}

// ---------------- split-bf16 MMA projection GEMM (layer0 only) --------------
#define P_ASZ (128 * 40)
#define P_BSZ (64 * 40)
#define P_BUF (2 * P_ASZ + 2 * P_BSZ)
__global__ __launch_bounds__(256) void mma_xproj(
    const __nv_bfloat16* __restrict__ Ahi, const __nv_bfloat16* __restrict__ Alo,
    const __nv_bfloat16* __restrict__ Whi, const __nv_bfloat16* __restrict__ Wlo,
    const float* __restrict__ b1, const float* __restrict__ b2,
    float* __restrict__ Cout, int K)
{
    extern __shared__ __nv_bfloat16 psm[];
    __shared__ float sBias[64];

    int tid = threadIdx.x;
    int n0 = blockIdx.x * 64;
    int m0 = blockIdx.y * 128;
    int w = tid >> 5, lane = tid & 31;
    int r0 = w * 16;

    if (tid < 64) sBias[tid] = b1[n0 + tid] + b2[n0 + tid];

    float acc[8][4];
#pragma unroll
    for (int i = 0; i < 8; i++)
#pragma unroll
        for (int j = 0; j < 4; j++) acc[i][j] = 0.f;

    size_t arow[2]; int aoff[2];
#pragma unroll
    for (int it = 0; it < 2; it++) {
        int idx = tid + it * 256;
        int r = idx >> 2, seg = idx & 3;
        int m = m0 + r;
        // A = x split [b][t][I]: row m = t*B+b
        arow[it] = ((size_t)(m & 63) * T_ + (size_t)(m >> 6)) * (size_t)K + (size_t)(seg * 8);
        aoff[it] = r * 40 + seg * 8;
    }
    int br = tid >> 2, bseg = tid & 3;
    size_t brow = (size_t)(n0 + br) * (size_t)K + (size_t)(bseg * 8);
    int boff = br * 40 + bseg * 8;

    int lrA = (lane & 7) + (lane & 8);
    int lcA = (lane & 16) ? 8 : 0;
    int lrB = lane & 7;
    int lcB = (lane & 8) ? 8 : 0;

    uint32_t dAhi[2], dAlo[2], dBhi[2], dBlo[2];
    uint32_t aHiB[2], aLoB[2], bHiB[2], bLoB[2];
#pragma unroll
    for (int buf = 0; buf < 2; buf++) {
        uint32_t base = cvta_s(psm + buf * P_BUF);
        dAhi[buf] = base;
        dAlo[buf] = base + P_ASZ * 2;
        dBhi[buf] = base + 2 * P_ASZ * 2;
        dBlo[buf] = base + (2 * P_ASZ + P_BSZ) * 2;
        aHiB[buf] = dAhi[buf] + (uint32_t)(((r0 + lrA) * 40 + lcA) * 2);
        aLoB[buf] = dAlo[buf] + (uint32_t)(((r0 + lrA) * 40 + lcA) * 2);
        bHiB[buf] = dBhi[buf] + (uint32_t)((lrB * 40 + lcB) * 2);
        bLoB[buf] = dBlo[buf] + (uint32_t)((lrB * 40 + lcB) * 2);
    }

#define PREFP(kc, buf) do {                                                   \
    _Pragma("unroll")                                                         \
    for (int it = 0; it < 2; it++) {                                          \
        CP_ASYNC16(dAhi[(buf)] + (uint32_t)(aoff[it] * 2), Ahi + arow[it] + (kc)); \
        CP_ASYNC16(dAlo[(buf)] + (uint32_t)(aoff[it] * 2), Alo + arow[it] + (kc)); \
    }                                                                         \
    CP_ASYNC16(dBhi[(buf)] + (uint32_t)(boff * 2), Whi + brow + (kc));        \
    CP_ASYNC16(dBlo[(buf)] + (uint32_t)(boff * 2), Wlo + brow + (kc));        \
    CP_COMMIT();                                                              \
} while (0)

    PREFP(0, 0);

    for (int kc = 0; kc < K; kc += 32) {
        int buf = (kc >> 5) & 1;
        CP_WAIT0();
        __syncthreads();
        if (kc + 32 < K) PREFP(kc + 32, buf ^ 1);
#pragma unroll
        for (int ks = 0; ks < 2; ks++) {
            int k0 = ks * 16;
            uint32_t ah[4], al[4];
            ldsm4(ah, aHiB[buf] + (uint32_t)(k0 * 2));
            ldsm4(al, aLoB[buf] + (uint32_t)(k0 * 2));
#pragma unroll
            for (int nt = 0; nt < 8; nt++) {
                uint32_t bh[2], bl[2];
                uint32_t off = (uint32_t)(nt * 8 * 40 + k0) * 2u;
                ldsm2(bh, bHiB[buf] + off);
                ldsm2(bl, bLoB[buf] + off);
                mma16816(acc[nt], ah, bh);
                mma16816(acc[nt], ah, bl);
                mma16816(acc[nt], al, bh);
            }
        }
        __syncthreads();
    }
#undef PREFP

    int g = lane >> 2, tq = lane & 3;
#pragma unroll
    for (int nt = 0; nt < 8; nt++) {
        int col = nt * 8 + tq * 2;
        float bb0 = sBias[col], bb1 = sBias[col + 1];
        size_t mA = (size_t)(m0 + r0 + g) * G_ + n0 + col;
        size_t mB = (size_t)(m0 + r0 + g + 8) * G_ + n0 + col;
        float2 v0 = make_float2(acc[nt][0] + bb0, acc[nt][1] + bb1);
        float2 v1 = make_float2(acc[nt][2] + bb0, acc[nt][3] + bb1);
        *(float2*)&Cout[mA] = v0;
        *(float2*)&Cout[mB] = v1;
    }
}
#define SMEM_PROJ (P_BUF * 2 * 2)

// ---------------- FUSED 2-layer LSTM recurrence ------------------------------
// 128 blocks x 512 threads, 513 fused steps. Block bid owns h0-cols and
// h1-cols [8bid, 8bid+8). At step t: layer0 computes h0[t] (t<512) from
// h0[t-1]; layer1 computes h1[t-1] (t>=1) from h0[t-1], h1[t-2].
// Warps 0-7: GEMM-A = [W_hh0 | W_ih1] (64 gate-cols) x h0[t-1].
// Warps 8-15: GEMM-B = W_hh1 (32 gate-cols) x h1[t-2].
// W_hh0 resident fp16 in SMEM; W_ih1/W_hh1 streamed fp16 from L2 per chunk.
extern __shared__ char smem_dyn[];
__global__ __launch_bounds__(512) void lstm_fused(
    const float* __restrict__ xproj,   // [T][B][4H] fp32 (layer0)
    const float* __restrict__ Whh0,    // [4H][H] fp32
    const float* __restrict__ bih1, const float* __restrict__ bhh1)
{
    __half* sW0 = (__half*)smem_dyn;            // 32 x 1032 resident
    __half* sH0 = sW0 + 32 * 1032;              // 2 x 64x136
    __half* sH1 = sH0 + 2 * 8704;               // 2 x 64x136
    __half* sWi = sH1 + 2 * 8704;               // 2 x 32x136 (W_ih1 stream)
    __half* sW1 = sWi + 2 * 4352;               // 2 x 32x136 (W_hh1 stream)
    float* sG01 = (float*)(sW1 + 2 * 4352);     // 64 x 66
    float* sG1  = sG01 + 64 * 66;               // 64 x 34
    float* sC0  = sG1 + 64 * 34;                // 512
    float* sC1  = sC0 + 512;                    // 512
    float* sB1  = sC1 + 512;                    // 32

    int tid = threadIdx.x, w = tid >> 5, lane = tid & 31;
    int bid = blockIdx.x;
    int jbase = bid * 8;

    // resident W_hh0 slice (fp16)
    for (int i = tid; i < 32 * 1024; i += 512) {
        int n = i >> 10, k = i & 1023;
        float v = Whh0[(size_t)((n >> 3) * H_ + jbase + (n & 7)) * H_ + k];
        sW0[n * 1032 + k] = __float2half(v);
    }
    if (tid < 32) {
        int gr = (tid >> 3) * H_ + jbase + (tid & 7);
        sB1[tid] = bih1[gr] + bhh1[gr];
    }
    sC0[tid] = 0.f;
    sC1[tid] = 0.f;

    // warp role + tile mapping
    int isA = (w < 8);
    int w2 = isA ? w : (w - 8);
    int rowg = w2 & 3, colg = w2 >> 2;
    int r0 = rowg * 16;
    int lrA = (lane & 7) + (lane & 8);
    int lcA = (lane & 16) ? 8 : 0;
    int bRow = lane & 7;
    int bK = ((lane >> 3) & 3) * 8;

    // A-frag bases (per buffer), on sH0 for A-warps, sH1 for B-warps
    __half* sHx = isA ? sH0 : sH1;
    uint32_t aA[2];
#pragma unroll
    for (int bf = 0; bf < 2; bf++)
        aA[bf] = cvta_s(&sHx[bf * 8704 + (r0 + lrA) * 136 + lcA]);

    // B bases
    // A-warps colg0: resident sW0 (stride 1032); colg1: streamed sWi (stride 136)
    uint32_t bRes[4], bStr[2][4];
#pragma unroll
    for (int ct = 0; ct < 4; ct++) {
        bRes[ct] = cvta_s(&sW0[(ct * 8 + bRow) * 1032 + bK]);
#pragma unroll
        for (int bf = 0; bf < 2; bf++)
            bStr[bf][ct] = cvta_s(&sWi[bf * 4352 + (ct * 8 + bRow) * 136 + bK]);
    }
    // B-warps: streamed sW1, 2 col-tiles at colg*16
    uint32_t bSt1[2][2];
#pragma unroll
    for (int ct = 0; ct < 2; ct++)
#pragma unroll
        for (int bf = 0; bf < 2; bf++)
            bSt1[bf][ct] = cvta_s(&sW1[bf * 4352 + (colg * 16 + ct * 8 + bRow) * 136 + bK]);

    // cp.async mappings
    uint32_t dH0[2], dH1[2], dWi[2], dW1[2];
#pragma unroll
    for (int bf = 0; bf < 2; bf++) {
        dH0[bf] = cvta_s(&sH0[bf * 8704]);
        dH1[bf] = cvta_s(&sH1[bf * 8704]);
        dWi[bf] = cvta_s(&sWi[bf * 4352]);
        dW1[bf] = cvta_s(&sW1[bf * 4352]);
    }
    int pr[2], ps[2];
#pragma unroll
    for (int it = 0; it < 2; it++) {
        int idx = tid + it * 512;
        pr[it] = idx >> 4;
        ps[it] = (idx & 15) * 8;
    }
    int wrow = tid >> 4;                 // 0..31 gate-col row for W streams
    int wseg = (tid & 15) * 8;
    uint32_t wso = (uint32_t)(wrow * 136 + wseg) * 2u;
    size_t wgrow = (size_t)((wrow >> 3) * H_ + jbase + (wrow & 7)) * (size_t)H_;
    const __half* gWi = g_wi1h;
    const __half* gW1 = g_wh1h;

    // gate-write mapping
    int g = lane >> 2, tq = lane & 3;
    int bA = r0 + g, bB = bA + 8;
    int cA = colg * 32;                  // A-warps: combined col base
    int c1 = colg * 16;                  // B-warps

    // cell mapping
    int cb = tid >> 3, cj = tid & 7;
    const float* xpb = xproj + (size_t)cb * G_ + jbase + cj;

    __syncthreads();

#define PREF(ch, bf) do {                                                     \
    int kc_ = (ch) * 128;                                                     \
    _Pragma("unroll")                                                         \
    for (int it = 0; it < 2; it++) {                                          \
        uint32_t so = (uint32_t)(pr[it] * 136 + ps[it]) * 2u;                 \
        CP_ASYNC16(dH0[(bf)] + so, hr0 + pr[it] * H_ + kc_ + ps[it]);         \
        CP_ASYNC16(dH1[(bf)] + so, hr1 + pr[it] * H_ + kc_ + ps[it]);         \
    }                                                                         \
    CP_ASYNC16(dWi[(bf)] + wso, gWi + wgrow + kc_ + wseg);                    \
    CP_ASYNC16(dW1[(bf)] + wso, gW1 + wgrow + kc_ + wseg);                    \
    CP_COMMIT();                                                              \
} while (0)

    for (int t = 0; t <= T_; t++) {
        const __half* hr0 = g_h0[(t + 1) & 1];   // h0[t-1]
        const __half* hr1 = g_h1[t & 1];         // h1[t-2]

        PREF(0, 0);

        float xg0 = 0.f, xg1 = 0.f, xg2 = 0.f, xg3 = 0.f;
        if (t < T_) {
            size_t xt = (size_t)t * B_ * G_;
            xg0 = xpb[xt];
            xg1 = xpb[xt + 1 * H_];
            xg2 = xpb[xt + 2 * H_];
            xg3 = xpb[xt + 3 * H_];
        }

        float acc[4][4];
#pragma unroll
        for (int i = 0; i < 4; i++)
#pragma unroll
            for (int j = 0; j < 4; j++) acc[i][j] = 0.f;

        for (int ch = 0; ch < 8; ch++) {
            int cur = ch & 1;
            CP_WAIT0();
            __syncthreads();
            if (ch < 7) PREF(ch + 1, cur ^ 1);

            int kc = ch * 128;
            if (isA) {
#pragma unroll
                for (int kg = 0; kg < 4; kg++) {
                    uint32_t koff = (uint32_t)(kg * 32) * 2u;
                    uint32_t a0[4], a1[4];
                    ldsm4(a0, aA[cur] + koff);
                    ldsm4(a1, aA[cur] + koff + 32);
#pragma unroll
                    for (int ct = 0; ct < 4; ct++) {
                        uint32_t b[4];
                        uint32_t addr = colg ? (bStr[cur][ct] + koff)
                                             : (bRes[ct] + (uint32_t)(kc + kg * 32) * 2u);
                        ldsm4(b, addr);
                        mma16816h(acc[ct], a0, b);
                        mma16816h(acc[ct], a1, b + 2);
                    }
                }
            } else {
#pragma unroll
                for (int kg = 0; kg < 4; kg++) {
                    uint32_t koff = (uint32_t)(kg * 32) * 2u;
                    uint32_t a0[4], a1[4];
                    ldsm4(a0, aA[cur] + koff);
                    ldsm4(a1, aA[cur] + koff + 32);
#pragma unroll
                    for (int ct = 0; ct < 2; ct++) {
                        uint32_t b[4];
                        ldsm4(b, bSt1[cur][ct] + koff);
                        mma16816h(acc[ct], a0, b);
                        mma16816h(acc[ct], a1, b + 2);
                    }
                }
            }
            __syncthreads();
        }

        // gate writes
        if (isA) {
#pragma unroll
            for (int ct = 0; ct < 4; ct++) {
                int col = cA + ct * 8 + tq * 2;
                *(float2*)&sG01[bA * 66 + col] = make_float2(acc[ct][0], acc[ct][1]);
                *(float2*)&sG01[bB * 66 + col] = make_float2(acc[ct][2], acc[ct][3]);
            }
        } else {
#pragma unroll
            for (int ct = 0; ct < 2; ct++) {
                int col = c1 + ct * 8 + tq * 2;
                *(float2*)&sG1[bA * 34 + col] = make_float2(acc[ct][0], acc[ct][1]);
                *(float2*)&sG1[bB * 34 + col] = make_float2(acc[ct][2], acc[ct][3]);
            }
        }
        __syncthreads();

        // cell updates
        __half* wr0 = g_h0[t & 1];
        __half* wr1 = g_h1[(t + 1) & 1];
        if (t < T_) {
            float iv = sG01[cb * 66 + cj]      + xg0;
            float fv = sG01[cb * 66 + 8 + cj]  + xg1;
            float gv = sG01[cb * 66 + 16 + cj] + xg2;
            float ov = sG01[cb * 66 + 24 + cj] + xg3;
            float ig = fsigmoid(iv), fg = fsigmoid(fv);
            float gg = ftanh(gv), og = fsigmoid(ov);
            float cc = fg * sC0[tid] + ig * gg;
            sC0[tid] = cc;
            float hh = og * ftanh(cc);
            wr0[cb * H_ + jbase + cj] = __float2half(hh);
        }
        if (t >= 1) {
            float iv = sG01[cb * 66 + 32 + cj]      + sG1[cb * 34 + cj]      + sB1[cj];
            float fv = sG01[cb * 66 + 32 + 8 + cj]  + sG1[cb * 34 + 8 + cj]  + sB1[8 + cj];
            float gv = sG01[cb * 66 + 32 + 16 + cj] + sG1[cb * 34 + 16 + cj] + sB1[16 + cj];
            float ov = sG01[cb * 66 + 32 + 24 + cj] + sG1[cb * 34 + 24 + cj] + sB1[24 + cj];
            float ig = fsigmoid(iv), fg = fsigmoid(fv);
            float gg = ftanh(gv), og = fsigmoid(ov);
            float cc = fg * sC1[tid] + ig * gg;
            sC1[tid] = cc;
            float hh = og * ftanh(cc);
            wr1[cb * H_ + jbase + cj] = __float2half(hh);
            if (t == T_) g_hlast[cb * H_ + jbase + cj] = hh;
        }
        if (t < T_) gridbar2(t, bid);
    }
#undef PREF
}
#define SMEM_FUSED ((32*1032 + 2*8704*2 + 2*4352*2) * 2 + (64*66 + 64*34 + 512 + 512 + 32) * 4)

// ---------------- FC head ----------------
__global__ __launch_bounds__(256) void fc_kernel(
    const float* __restrict__ fc_w, const float* __restrict__ fc_b,
    float* __restrict__ out)
{
    __shared__ float sh[H_];
    int b = blockIdx.x, tid = threadIdx.x;
    const float* hlast = g_hlast + (size_t)b * H_;
    for (int i = tid; i < H_; i += 256) sh[i] = hlast[i];
    __syncthreads();
    int o = tid;
    const float* wrow = fc_w + (size_t)o * H_;
    float acc = fc_b[o];
#pragma unroll 8
    for (int k = 0; k < H_; k++) acc += sh[k] * wrow[k];
    out[b * O_ + o] = acc;
}

// ---------------- launch ----------------
extern "C" void kernel_launch(void* const* d_in, const int* in_sizes, int n_in,
                              void* d_out, int out_size) {
    (void)in_sizes; (void)n_in; (void)out_size;
    const float* x     = (const float*)d_in[0];
    const float* W_ih0 = (const float*)d_in[1];
    const float* W_hh0 = (const float*)d_in[2];
    const float* b_ih0 = (const float*)d_in[3];
    const float* b_hh0 = (const float*)d_in[4];
    const float* W_ih1 = (const float*)d_in[5];
    const float* W_hh1 = (const float*)d_in[6];
    const float* b_ih1 = (const float*)d_in[7];
    const float* b_hh1 = (const float*)d_in[8];
    const float* fc_w  = (const float*)d_in[9];
    const float* fc_b  = (const float*)d_in[10];
    float* out = (float*)d_out;

    float* xp0;
    __nv_bfloat16 *xhi, *xlo, *w0hi, *w0lo;
    __half *wi1h, *wh1h;
    cudaGetSymbolAddress((void**)&xp0, g_xproj0);
    cudaGetSymbolAddress((void**)&xhi, g_xhi);
    cudaGetSymbolAddress((void**)&xlo, g_xlo);
    cudaGetSymbolAddress((void**)&w0hi, g_wih0hi);
    cudaGetSymbolAddress((void**)&w0lo, g_wih0lo);
    cudaGetSymbolAddress((void**)&wi1h, g_wi1h);
    cudaGetSymbolAddress((void**)&wh1h, g_wh1h);

    cudaFuncSetAttribute(lstm_fused,
        cudaFuncAttributeMaxDynamicSharedMemorySize, SMEM_FUSED);
    cudaFuncSetAttribute(mma_xproj,
        cudaFuncAttributeMaxDynamicSharedMemorySize, SMEM_PROJ);

    // operand prep
    int nx4 = B_ * T_ * I_ / 4;
    split_kernel<<<(nx4 + 255) / 256, 256>>>(x, xhi, xlo, nx4);
    int nw04 = G_ * I_ / 4;
    split_kernel<<<(nw04 + 255) / 256, 256>>>(W_ih0, w0hi, w0lo, nw04);
    int nw14 = G_ * H_ / 4;
    conv_half<<<(nw14 + 255) / 256, 256>>>(W_ih1, wi1h, nw14);
    conv_half<<<(nw14 + 255) / 256, 256>>>(W_hh1, wh1h, nw14);

    // layer0 input projection
    dim3 pgrid(G_ / 64, (B_ * T_) / 128);
    mma_xproj<<<pgrid, 256, SMEM_PROJ>>>(xhi, xlo, w0hi, w0lo, b_ih0, b_hh0, xp0, I_);

    // fused 2-layer recurrence
    init_kernel<<<64, 256>>>();
    lstm_fused<<<128, 512, SMEM_FUSED>>>(xp0, W_hh0, b_ih1, b_hh1);

    // head
    fc_kernel<<<64, 256>>>(fc_w, fc_b, out);
}